// round 7
// baseline (speedup 1.0000x reference)
#include <cuda_runtime.h>
#include <math.h>
#include <float.h>

#define BATCH  2
#define SEQ    2048
#define DMODEL 1024
#define NHEAD  16
#define DHEAD  64
#define TOPK   32

#define BLK_M  64            // q-rows per fused CTA
#define CHUNK  64            // key columns per chunk
#define NCHUNK (SEQ / CHUNK) // 32

// ---------------- device scratch ----------------
__device__ float g_q[(size_t)BATCH * SEQ * DMODEL];
__device__ float g_k[(size_t)BATCH * SEQ * DMODEL];
__device__ float g_v[(size_t)BATCH * SEQ * DMODEL];
__device__ float g_ctx[(size_t)BATCH * SEQ * DMODEL];
__device__ float g_selv[(size_t)BATCH * NHEAD * SEQ * TOPK];  // 8.4 MB
__device__ int   g_seli[(size_t)BATCH * NHEAD * SEQ * TOPK];  // 8.4 MB

// =======================================================================================
// Projection kernel (Q, K, V via blockIdx.z). 256 thr, 2 CTAs/SM, 128m x 64n tile,
// 4x8 microtile, double-buffered SMEM. FFMA sequence bitwise identical to R2/R4/R5.
// =======================================================================================
__global__ __launch_bounds__(256, 2) void proj_kernel(
    const float* __restrict__ query, const float* __restrict__ key,
    const float* __restrict__ value,
    const float* __restrict__ Wq, const float* __restrict__ bq,
    const float* __restrict__ Wk, const float* __restrict__ bk,
    const float* __restrict__ Wv, const float* __restrict__ bv)
{
    __shared__ float As[2][16][132];
    __shared__ float Ws[2][16][68];

    const int z = blockIdx.z;
    const float* A    = (z == 0) ? query : (z == 1) ? key : value;
    const float* W    = (z == 0) ? Wq    : (z == 1) ? Wk  : Wv;
    const float* bias = (z == 0) ? bq    : (z == 1) ? bk  : bv;
    float*       C    = (z == 0) ? g_q   : (z == 1) ? g_k : g_v;

    const int tid = threadIdx.x;
    const int m0 = blockIdx.y * 128;
    const int n0 = blockIdx.x * 64;
    const int tr = tid >> 3;
    const int tc = tid & 7;

    const int ra = tid >> 1;
    const int ca = (tid & 1) << 3;
    const int rw = tid >> 2;
    const int cw = (tid & 3) << 2;

    const float* Arow = A + (size_t)(m0 + ra) * 1024 + ca;
    const float* Wrow = W + (size_t)(n0 + rw) * 1024 + cw;

    {
        float4 a0 = *(const float4*)(Arow);
        float4 a1 = *(const float4*)(Arow + 4);
        As[0][ca + 0][ra] = a0.x; As[0][ca + 1][ra] = a0.y;
        As[0][ca + 2][ra] = a0.z; As[0][ca + 3][ra] = a0.w;
        As[0][ca + 4][ra] = a1.x; As[0][ca + 5][ra] = a1.y;
        As[0][ca + 6][ra] = a1.z; As[0][ca + 7][ra] = a1.w;
        float4 w0 = *(const float4*)(Wrow);
        Ws[0][cw + 0][rw] = w0.x; Ws[0][cw + 1][rw] = w0.y;
        Ws[0][cw + 2][rw] = w0.z; Ws[0][cw + 3][rw] = w0.w;
    }
    __syncthreads();

    float acc[4][8], p[4][8];
#pragma unroll
    for (int i = 0; i < 4; i++)
#pragma unroll
        for (int j = 0; j < 8; j++) acc[i][j] = 0.f;

#pragma unroll 1
    for (int s = 0; s < 64; s++) {
        const int cur = s & 1;
        float4 na0, na1, nw0;
        if (s < 63) {
            na0 = *(const float4*)(Arow + (size_t)(s + 1) * 16);
            na1 = *(const float4*)(Arow + (size_t)(s + 1) * 16 + 4);
            nw0 = *(const float4*)(Wrow + (size_t)(s + 1) * 16);
        }
        const bool pinit = ((s & 3) == 0);
#pragma unroll
        for (int kk = 0; kk < 16; kk++) {
            float a[4], w[8];
            *(float4*)(a)     = *(const float4*)&As[cur][kk][tr * 4];
            *(float4*)(w)     = *(const float4*)&Ws[cur][kk][tc * 8];
            *(float4*)(w + 4) = *(const float4*)&Ws[cur][kk][tc * 8 + 4];
            if (pinit && kk == 0) {
#pragma unroll
                for (int i = 0; i < 4; i++)
#pragma unroll
                    for (int j = 0; j < 8; j++) p[i][j] = a[i] * w[j];
            } else {
#pragma unroll
                for (int i = 0; i < 4; i++)
#pragma unroll
                    for (int j = 0; j < 8; j++) p[i][j] += a[i] * w[j];
            }
        }
        if ((s & 3) == 3) {
#pragma unroll
            for (int i = 0; i < 4; i++)
#pragma unroll
                for (int j = 0; j < 8; j++) acc[i][j] += p[i][j];
        }
        if (s < 63) {
            const int nxt = cur ^ 1;
            As[nxt][ca + 0][ra] = na0.x; As[nxt][ca + 1][ra] = na0.y;
            As[nxt][ca + 2][ra] = na0.z; As[nxt][ca + 3][ra] = na0.w;
            As[nxt][ca + 4][ra] = na1.x; As[nxt][ca + 5][ra] = na1.y;
            As[nxt][ca + 6][ra] = na1.z; As[nxt][ca + 7][ra] = na1.w;
            Ws[nxt][cw + 0][rw] = nw0.x; Ws[nxt][cw + 1][rw] = nw0.y;
            Ws[nxt][cw + 2][rw] = nw0.z; Ws[nxt][cw + 3][rw] = nw0.w;
        }
        __syncthreads();
    }

    float bb[8];
#pragma unroll
    for (int j = 0; j < 8; j++) bb[j] = bias[n0 + tc * 8 + j];
#pragma unroll
    for (int i = 0; i < 4; i++) {
        float4 o0, o1;
        o0.x = acc[i][0] + bb[0]; o0.y = acc[i][1] + bb[1];
        o0.z = acc[i][2] + bb[2]; o0.w = acc[i][3] + bb[3];
        o1.x = acc[i][4] + bb[4]; o1.y = acc[i][5] + bb[5];
        o1.z = acc[i][6] + bb[6]; o1.w = acc[i][7] + bb[7];
        float* crow = C + (size_t)(m0 + tr * 4 + i) * 1024 + n0 + tc * 8;
        *(float4*)crow       = o0;
        *(float4*)(crow + 4) = o1;
    }
}

// =======================================================================================
// FUSED scores + mask + top-32 kernel. One CTA = 64 q-rows x all 2048 keys of one (b,h).
// K streamed in 64-col chunks (double-buffered; prefetch by threads 128..255 during scan).
// Per-score FFMA chain bitwise identical to R5 (k ascending 0..63, init at k=0, *0.125f).
// Exact top-32 per row under total order (value desc, index asc) == jax.lax.top_k set.
// Output: g_selv/g_seli in descending pop order (selv[0] = row max), as R5's selv/seli.
// SMEM layout (floats):
//   Qs  [64][68]           k-major Q tile
//   Ks  [2][64][68]        k-major K chunk, double buffered
//   Sb  [64][68]           chunk scores
//   Lv  [128][33]          per-scan-thread top-32 values (pad 33: conflict-free)
//   Li  [128][33]          per-scan-thread top-32 indices
// =======================================================================================
#define QS(k, r)     smf[(k) * 68 + (r)]
#define KS(bf, k, c) smf[4352 + (bf) * 4352 + (k) * 68 + (c)]
#define SB(r, c)     smf[13056 + (r) * 68 + (c)]
#define LV(t, j)     smf[17408 + (t) * 33 + (j)]
#define LI(t, j)     smi[21632 + (t) * 33 + (j)]
#define FUSED_SMEM   ((21632 + 128 * 33) * 4)   // 103,424 bytes

__global__ __launch_bounds__(256, 2) void fused_scores_topk_kernel(const int* __restrict__ mask)
{
    extern __shared__ float smf[];
    int* smi = (int*)smf;

    const int z = blockIdx.y;        // b*NHEAD + h
    const int b = z >> 4;
    const int h = z & 15;
    const int m0 = blockIdx.x * BLK_M;
    const int tid = threadIdx.x;     // 0..255
    const int tr = tid >> 4;         // 0..15 -> score rows tr*4..+3
    const int tc = tid & 15;         // 0..15 -> score cols tc*4..+3

    const float* Qb = g_q + (size_t)b * SEQ * DMODEL + h * DHEAD;
    const float* Kb = g_k + (size_t)b * SEQ * DMODEL + h * DHEAD;

    // ---- stage Q tile [64 rows x 64 k], k-major ----
    {
        const int row = tid >> 2;            // 0..63
        const int kq  = (tid & 3) << 4;      // 0,16,32,48
        const float* qr = Qb + (size_t)(m0 + row) * DMODEL + kq;
#pragma unroll
        for (int i = 0; i < 4; i++) {
            float4 v = *(const float4*)(qr + i * 4);
            QS(kq + i * 4 + 0, row) = v.x; QS(kq + i * 4 + 1, row) = v.y;
            QS(kq + i * 4 + 2, row) = v.z; QS(kq + i * 4 + 3, row) = v.w;
        }
        // ---- stage K chunk 0 into buffer 0 ----
        const float* kr = Kb + (size_t)row * DMODEL + kq;
#pragma unroll
        for (int i = 0; i < 4; i++) {
            float4 v = *(const float4*)(kr + i * 4);
            KS(0, kq + i * 4 + 0, row) = v.x; KS(0, kq + i * 4 + 1, row) = v.y;
            KS(0, kq + i * 4 + 2, row) = v.z; KS(0, kq + i * 4 + 3, row) = v.w;
        }
    }
    __syncthreads();

    // per-scan-thread top-k state (threads 0..127: row = tid>>1, half = tid&1)
    int cnt = 0, worstidx = 0, worstpos = 0;
    float worstv = 0.f;
    const int srow  = tid >> 1;
    const int shalf = tid & 1;
    const int* mrow_base = mask + ((size_t)b * SEQ + (m0 + srow)) * SEQ + shalf * 32;

#pragma unroll 1
    for (int c = 0; c < NCHUNK; c++) {
        const int cur = c & 1;

        // ---- GEMM: 64x64 chunk, 4x4 per thread, k ascending, init at k==0 ----
        float acc[4][4];
#pragma unroll 8
        for (int kk = 0; kk < 64; kk++) {
            float a[4], w[4];
            *(float4*)(a) = *(const float4*)&QS(kk, tr * 4);
            *(float4*)(w) = *(const float4*)&KS(cur, kk, tc * 4);
            if (kk == 0) {
#pragma unroll
                for (int i = 0; i < 4; i++)
#pragma unroll
                    for (int j = 0; j < 4; j++) acc[i][j] = a[i] * w[j];
            } else {
#pragma unroll
                for (int i = 0; i < 4; i++)
#pragma unroll
                    for (int j = 0; j < 4; j++) acc[i][j] += a[i] * w[j];
            }
        }
#pragma unroll
        for (int i = 0; i < 4; i++) {
            float4 o;
            o.x = acc[i][0] * 0.125f; o.y = acc[i][1] * 0.125f;
            o.z = acc[i][2] * 0.125f; o.w = acc[i][3] * 0.125f;
            *(float4*)&SB(tr * 4 + i, tc * 4) = o;
        }
        __syncthreads();

        // ---- phase 2: scan (tid<128) | prefetch next K chunk (tid>=128) ----
        if (tid < 128) {
            const int c0g = c * CHUNK + shalf * 32;     // global col of lc==0
            const int* mrow = mrow_base + c * CHUNK;
#pragma unroll 4
            for (int lc = 0; lc < 32; lc++) {
                float v = SB(srow, shalf * 32 + lc);
                if (mrow[lc] == 0) v = -1e9f;
                const int idx = c0g + lc;
                if (cnt < 32) {
                    LV(tid, cnt) = v; LI(tid, cnt) = idx;
                    if (cnt == 0 || v < worstv) { worstv = v; worstidx = idx; worstpos = cnt; }
                    else if (v == worstv && idx > worstidx) { worstidx = idx; worstpos = cnt; }
                    cnt++;
                } else if (v > worstv || (v == worstv && idx < worstidx)) {
                    LV(tid, worstpos) = v; LI(tid, worstpos) = idx;
                    worstv = LV(tid, 0); worstidx = LI(tid, 0); worstpos = 0;
#pragma unroll 4
                    for (int t2 = 1; t2 < 32; t2++) {
                        float tv = LV(tid, t2); int ti = LI(tid, t2);
                        if (tv < worstv || (tv == worstv && ti > worstidx)) {
                            worstv = tv; worstidx = ti; worstpos = t2;
                        }
                    }
                }
            }
        } else if (c + 1 < NCHUNK) {
            const int u    = tid - 128;
            const int row  = u >> 1;             // chunk col 0..63
            const int koff = (u & 1) << 5;       // 0 or 32
            const int nbuf = cur ^ 1;
            const float* kr = Kb + (size_t)((c + 1) * CHUNK + row) * DMODEL + koff;
#pragma unroll
            for (int i = 0; i < 8; i++) {
                float4 v = *(const float4*)(kr + i * 4);
                KS(nbuf, koff + i * 4 + 0, row) = v.x; KS(nbuf, koff + i * 4 + 1, row) = v.y;
                KS(nbuf, koff + i * 4 + 2, row) = v.z; KS(nbuf, koff + i * 4 + 3, row) = v.w;
            }
        }
        __syncthreads();
    }

    // ---- merge two half-lists per row; pop 32 in descending (v desc, idx asc) order ----
    if (tid < BLK_M) {
        const int tA = 2 * tid, tB = 2 * tid + 1;
        const size_t rbase = ((size_t)z * SEQ + m0 + tid) * TOPK;
        float* outv = g_selv + rbase;
        int*   outi = g_seli + rbase;
#pragma unroll 1
        for (int it = 0; it < TOPK; it++) {
            float bv = -INFINITY; int bi = 0x7fffffff; int bp = -1;
#pragma unroll 4
            for (int j = 0; j < 32; j++) {
                float v = LV(tA, j); int ix = LI(tA, j);
                if (v > bv || (v == bv && ix < bi)) { bv = v; bi = ix; bp = j; }
            }
#pragma unroll 4
            for (int j = 0; j < 32; j++) {
                float v = LV(tB, j); int ix = LI(tB, j);
                if (v > bv || (v == bv && ix < bi)) { bv = v; bi = ix; bp = 32 + j; }
            }
            outv[it] = bv; outi[it] = bi;
            if (bp < 32) LV(tA, bp) = -INFINITY; else LV(tB, bp - 32) = -INFINITY;
        }
    }
}

// =======================================================================================
// Softmax + V gather. One warp per (z, q) row. selv is descending -> selv[0] is row max;
// butterfly-sum order identical to R5's gather.
// =======================================================================================
__global__ __launch_bounds__(128) void topk_gather_kernel()
{
    const int warp = threadIdx.x >> 5;
    const int lane = threadIdx.x & 31;
    const int rid = blockIdx.x * 4 + warp;   // z*SEQ + q
    const int q = rid & (SEQ - 1);
    const int z = rid >> 11;
    const int b = z >> 4;
    const int h = z & 15;

    const float v   = g_selv[(size_t)rid * TOPK + lane];
    const int   idx = g_seli[(size_t)rid * TOPK + lane];
    const float vmax = __shfl_sync(0xffffffffu, v, 0);
    float e = expf(v - vmax);
    float ssum = e;
#pragma unroll
    for (int off = 16; off; off >>= 1) ssum += __shfl_xor_sync(0xffffffffu, ssum, off);
    const float p = e / ssum;

    const float* vb = g_v + (size_t)b * SEQ * DMODEL + h * DHEAD;
    float acc0 = 0.f, acc1 = 0.f;
#pragma unroll 4
    for (int j = 0; j < TOPK; j++) {
        float pj = __shfl_sync(0xffffffffu, p, j);
        int ij   = __shfl_sync(0xffffffffu, idx, j);
        const float* vr = vb + (size_t)ij * DMODEL;
        acc0 += pj * vr[lane];
        acc1 += pj * vr[lane + 32];
    }
    float* crow = g_ctx + ((size_t)(b * SEQ + q)) * DMODEL + h * DHEAD;
    crow[lane]      = acc0;
    crow[lane + 32] = acc1;
}

// =======================================================================================
// FAST fp32 NT GEMM (256 thr, 8x8 microtile) — output projection only.
// =======================================================================================
__global__ __launch_bounds__(256, 2) void out_gemm_kernel(
    float* __restrict__ C, const float* __restrict__ W, const float* __restrict__ bias)
{
    __shared__ float As[16][132];
    __shared__ float Ws[16][132];
    const float* A = g_ctx;
    const int tid = threadIdx.x;
    const int m0 = blockIdx.y * 128;
    const int n0 = blockIdx.x * 128;
    const int tr = tid >> 4;
    const int tc = tid & 15;
    float acc[8][8];
#pragma unroll
    for (int i = 0; i < 8; i++)
#pragma unroll
        for (int j = 0; j < 8; j++) acc[i][j] = 0.f;

    const int r0 = tid >> 2;
    const int c0 = (tid & 3) << 2;

    for (int k0 = 0; k0 < 1024; k0 += 16) {
#pragma unroll
        for (int t = 0; t < 2; t++) {
            int r = r0 + t * 64;
            float4 av = *(const float4*)(A + (size_t)(m0 + r) * 1024 + k0 + c0);
            As[c0 + 0][r] = av.x; As[c0 + 1][r] = av.y;
            As[c0 + 2][r] = av.z; As[c0 + 3][r] = av.w;
            float4 wv = *(const float4*)(W + (size_t)(n0 + r) * 1024 + k0 + c0);
            Ws[c0 + 0][r] = wv.x; Ws[c0 + 1][r] = wv.y;
            Ws[c0 + 2][r] = wv.z; Ws[c0 + 3][r] = wv.w;
        }
        __syncthreads();
#pragma unroll
        for (int k = 0; k < 16; k++) {
            float a[8], w[8];
            *(float4*)(a)     = *(const float4*)&As[k][tr * 8];
            *(float4*)(a + 4) = *(const float4*)&As[k][tr * 8 + 4];
            *(float4*)(w)     = *(const float4*)&Ws[k][tc * 8];
            *(float4*)(w + 4) = *(const float4*)&Ws[k][tc * 8 + 4];
#pragma unroll
            for (int i = 0; i < 8; i++)
#pragma unroll
                for (int j = 0; j < 8; j++)
                    acc[i][j] += a[i] * w[j];
        }
        __syncthreads();
    }

    float bb[8];
#pragma unroll
    for (int j = 0; j < 8; j++) bb[j] = bias[n0 + tc * 8 + j];
#pragma unroll
    for (int i = 0; i < 8; i++) {
        float4 o0, o1;
        o0.x = acc[i][0] + bb[0]; o0.y = acc[i][1] + bb[1];
        o0.z = acc[i][2] + bb[2]; o0.w = acc[i][3] + bb[3];
        o1.x = acc[i][4] + bb[4]; o1.y = acc[i][5] + bb[5];
        o1.z = acc[i][6] + bb[6]; o1.w = acc[i][7] + bb[7];
        float* crow = C + (size_t)(m0 + tr * 8 + i) * 1024 + n0 + tc * 8;
        *(float4*)crow       = o0;
        *(float4*)(crow + 4) = o1;
    }
}

// ---------------- launch ----------------
extern "C" void kernel_launch(void* const* d_in, const int* in_sizes, int n_in,
                              void* d_out, int out_size)
{
    const float* query = (const float*)d_in[0];
    const float* key   = (const float*)d_in[1];
    const float* value = (const float*)d_in[2];
    const float* Wq    = (const float*)d_in[3];
    const float* bq    = (const float*)d_in[4];
    const float* Wk    = (const float*)d_in[5];
    const float* bk    = (const float*)d_in[6];
    const float* Wv    = (const float*)d_in[7];
    const float* bv    = (const float*)d_in[8];
    const float* Wo    = (const float*)d_in[9];
    const float* bo    = (const float*)d_in[10];
    const int*   mask  = (const int*)d_in[11];
    (void)in_sizes; (void)n_in; (void)out_size;

    cudaFuncSetAttribute(fused_scores_topk_kernel,
                         cudaFuncAttributeMaxDynamicSharedMemorySize, FUSED_SMEM);

    dim3 gp(DMODEL / 64, (BATCH * SEQ) / 128, 3);          // (16, 32, 3)
    proj_kernel<<<gp, 256>>>(query, key, value, Wq, bq, Wk, bk, Wv, bv);

    dim3 gf(SEQ / BLK_M, BATCH * NHEAD);                   // (32, 32)
    fused_scores_topk_kernel<<<gf, 256, FUSED_SMEM>>>(mask);

    topk_gather_kernel<<<(BATCH * NHEAD * SEQ) / 4, 128>>>();

    dim3 go(DMODEL / 128, (BATCH * SEQ) / 128);            // (8, 32)
    out_gemm_kernel<<<go, 256>>>((float*)d_out, Wo, bo);
}

// round 8
// speedup vs baseline: 1.9260x; 1.9260x over previous
#include <cuda_runtime.h>
#include <math.h>
#include <float.h>

#define BATCH  2
#define SEQ    2048
#define DMODEL 1024
#define NHEAD  16
#define DHEAD  64
#define TOPK   32

#define BLK_M  64            // q-rows per fused CTA
#define CHUNK  64            // key columns per chunk
#define NCHUNK (SEQ / CHUNK) // 32

// ---------------- device scratch ----------------
__device__ float g_q[(size_t)BATCH * SEQ * DMODEL];
__device__ float g_k[(size_t)BATCH * SEQ * DMODEL];
__device__ float g_v[(size_t)BATCH * SEQ * DMODEL];
__device__ float g_ctx[(size_t)BATCH * SEQ * DMODEL];

// ---------------- cp.async helpers ----------------
__device__ __forceinline__ unsigned smem_u32(const void* p) {
    unsigned r;
    asm("{ .reg .u64 t; cvta.to.shared.u64 t, %1; cvt.u32.u64 %0, t; }" : "=r"(r) : "l"(p));
    return r;
}
#define CP_ASYNC16(dst, src) \
    asm volatile("cp.async.cg.shared.global [%0], [%1], 16;" :: "r"(dst), "l"(src))
#define CP_COMMIT() asm volatile("cp.async.commit_group;")
#define CP_WAIT0()  asm volatile("cp.async.wait_group 0;")

// =======================================================================================
// Projection kernel (Q, K, V via blockIdx.z) — unchanged from R5 (proven).
// =======================================================================================
__global__ __launch_bounds__(256, 2) void proj_kernel(
    const float* __restrict__ query, const float* __restrict__ key,
    const float* __restrict__ value,
    const float* __restrict__ Wq, const float* __restrict__ bq,
    const float* __restrict__ Wk, const float* __restrict__ bk,
    const float* __restrict__ Wv, const float* __restrict__ bv)
{
    __shared__ float As[2][16][132];
    __shared__ float Ws[2][16][68];

    const int z = blockIdx.z;
    const float* A    = (z == 0) ? query : (z == 1) ? key : value;
    const float* W    = (z == 0) ? Wq    : (z == 1) ? Wk  : Wv;
    const float* bias = (z == 0) ? bq    : (z == 1) ? bk  : bv;
    float*       C    = (z == 0) ? g_q   : (z == 1) ? g_k : g_v;

    const int tid = threadIdx.x;
    const int m0 = blockIdx.y * 128;
    const int n0 = blockIdx.x * 64;
    const int tr = tid >> 3;
    const int tc = tid & 7;

    const int ra = tid >> 1;
    const int ca = (tid & 1) << 3;
    const int rw = tid >> 2;
    const int cw = (tid & 3) << 2;

    const float* Arow = A + (size_t)(m0 + ra) * 1024 + ca;
    const float* Wrow = W + (size_t)(n0 + rw) * 1024 + cw;

    {
        float4 a0 = *(const float4*)(Arow);
        float4 a1 = *(const float4*)(Arow + 4);
        As[0][ca + 0][ra] = a0.x; As[0][ca + 1][ra] = a0.y;
        As[0][ca + 2][ra] = a0.z; As[0][ca + 3][ra] = a0.w;
        As[0][ca + 4][ra] = a1.x; As[0][ca + 5][ra] = a1.y;
        As[0][ca + 6][ra] = a1.z; As[0][ca + 7][ra] = a1.w;
        float4 w0 = *(const float4*)(Wrow);
        Ws[0][cw + 0][rw] = w0.x; Ws[0][cw + 1][rw] = w0.y;
        Ws[0][cw + 2][rw] = w0.z; Ws[0][cw + 3][rw] = w0.w;
    }
    __syncthreads();

    float acc[4][8], p[4][8];
#pragma unroll
    for (int i = 0; i < 4; i++)
#pragma unroll
        for (int j = 0; j < 8; j++) acc[i][j] = 0.f;

#pragma unroll 1
    for (int s = 0; s < 64; s++) {
        const int cur = s & 1;
        float4 na0, na1, nw0;
        if (s < 63) {
            na0 = *(const float4*)(Arow + (size_t)(s + 1) * 16);
            na1 = *(const float4*)(Arow + (size_t)(s + 1) * 16 + 4);
            nw0 = *(const float4*)(Wrow + (size_t)(s + 1) * 16);
        }
        const bool pinit = ((s & 3) == 0);
#pragma unroll
        for (int kk = 0; kk < 16; kk++) {
            float a[4], w[8];
            *(float4*)(a)     = *(const float4*)&As[cur][kk][tr * 4];
            *(float4*)(w)     = *(const float4*)&Ws[cur][kk][tc * 8];
            *(float4*)(w + 4) = *(const float4*)&Ws[cur][kk][tc * 8 + 4];
            if (pinit && kk == 0) {
#pragma unroll
                for (int i = 0; i < 4; i++)
#pragma unroll
                    for (int j = 0; j < 8; j++) p[i][j] = a[i] * w[j];
            } else {
#pragma unroll
                for (int i = 0; i < 4; i++)
#pragma unroll
                    for (int j = 0; j < 8; j++) p[i][j] += a[i] * w[j];
            }
        }
        if ((s & 3) == 3) {
#pragma unroll
            for (int i = 0; i < 4; i++)
#pragma unroll
                for (int j = 0; j < 8; j++) acc[i][j] += p[i][j];
        }
        if (s < 63) {
            const int nxt = cur ^ 1;
            As[nxt][ca + 0][ra] = na0.x; As[nxt][ca + 1][ra] = na0.y;
            As[nxt][ca + 2][ra] = na0.z; As[nxt][ca + 3][ra] = na0.w;
            As[nxt][ca + 4][ra] = na1.x; As[nxt][ca + 5][ra] = na1.y;
            As[nxt][ca + 6][ra] = na1.z; As[nxt][ca + 7][ra] = na1.w;
            Ws[nxt][cw + 0][rw] = nw0.x; Ws[nxt][cw + 1][rw] = nw0.y;
            Ws[nxt][cw + 2][rw] = nw0.z; Ws[nxt][cw + 3][rw] = nw0.w;
        }
        __syncthreads();
    }

    float bb[8];
#pragma unroll
    for (int j = 0; j < 8; j++) bb[j] = bias[n0 + tc * 8 + j];
#pragma unroll
    for (int i = 0; i < 4; i++) {
        float4 o0, o1;
        o0.x = acc[i][0] + bb[0]; o0.y = acc[i][1] + bb[1];
        o0.z = acc[i][2] + bb[2]; o0.w = acc[i][3] + bb[3];
        o1.x = acc[i][4] + bb[4]; o1.y = acc[i][5] + bb[5];
        o1.z = acc[i][6] + bb[6]; o1.w = acc[i][7] + bb[7];
        float* crow = C + (size_t)(m0 + tr * 4 + i) * 1024 + n0 + tc * 8;
        *(float4*)crow       = o0;
        *(float4*)(crow + 4) = o1;
    }
}

// =======================================================================================
// FUSED scores + mask + top-32 + softmax + V-gather (v2: warp-cooperative sorted lists).
// CTA = 64 q-rows x 2048 keys of one (b,h). GEMM bitwise identical to R6/R7 (proven).
// Each warp owns 8 rows; a row's top-32 is a register list, one entry per lane, sorted
// descending under the total order (value desc, index asc). Inserts are warp-uniform.
// Mask tiles stream through SMEM via cp.async (double-buffered); K via register prefetch.
// Epilogue does softmax + V gather directly (same op order as R5/R7 gather) -> g_ctx.
// SMEM words: Qs[64][68]=4352 | Ks[2][64][68]=8704 | Sb[64][68]=4352 | Ms[2][64][64]=8192
// =======================================================================================
#define QS(k, r)     smf[(k) * 68 + (r)]
#define KS(bf, k, c) smf[4352 + (bf) * 4352 + (k) * 68 + (c)]
#define SB(r, c)     smf[13056 + (r) * 68 + (c)]
#define MS(bf, r, c) smi[17408 + (bf) * 4096 + (r) * 64 + (c)]
#define FUSED_SMEM   (25600 * 4)   // 102,400 bytes

__device__ __forceinline__ void topk_insert_pass(
    float v, int idx, float& lvI, int& liI, int lane)
{
    float tv = __shfl_sync(0xffffffffu, lvI, 31);
    int   ti = __shfl_sync(0xffffffffu, liI, 31);
    bool pass = (v > tv) || (v == tv && idx < ti);
    unsigned m = __ballot_sync(0xffffffffu, pass);
    while (m) {
        const int src = __ffs(m) - 1; m &= m - 1;
        const float cv = __shfl_sync(0xffffffffu, v, src);
        const int   ci = __shfl_sync(0xffffffffu, idx, src);
        if ((cv > tv) || (cv == tv && ci < ti)) {      // uniform re-verify
            bool mb = (lvI > cv) || (lvI == cv && liI < ci);
            unsigned bm = __ballot_sync(0xffffffffu, mb);
            const int pos = __popc(bm);                // sorted list -> beats-set is prefix
            float sv = __shfl_up_sync(0xffffffffu, lvI, 1);
            int   si = __shfl_up_sync(0xffffffffu, liI, 1);
            if (lane > pos)       { lvI = sv; liI = si; }
            else if (lane == pos) { lvI = cv; liI = ci; }
            tv = __shfl_sync(0xffffffffu, lvI, 31);
            ti = __shfl_sync(0xffffffffu, liI, 31);
        }
    }
}

__global__ __launch_bounds__(256, 2) void fused_attn_kernel(const int* __restrict__ mask)
{
    extern __shared__ float smf[];
    int* smi = (int*)smf;
    const unsigned sbase = smem_u32(smf);

    const int z = blockIdx.y;        // b*NHEAD + h
    const int b = z >> 4;
    const int h = z & 15;
    const int m0 = blockIdx.x * BLK_M;
    const int tid = threadIdx.x;     // 0..255
    const int warp = tid >> 5;
    const int lane = tid & 31;
    const int tr = tid >> 4;         // GEMM: rows tr*4..+3
    const int tc = tid & 15;         // GEMM: cols tc*4..+3

    const float* Qb = g_q + (size_t)b * SEQ * DMODEL + h * DHEAD;
    const float* Kb = g_k + (size_t)b * SEQ * DMODEL + h * DHEAD;

    // ---- staging thread roles: row = tid>>2 (0..63), quarter = tid&3 ----
    const int strow = tid >> 2;
    const int stq   = tid & 3;

    // stage Q tile + K chunk 0 (transpose to k-major, as R6)
    {
        const int kq = stq << 4;
        const float* qr = Qb + (size_t)(m0 + strow) * DMODEL + kq;
#pragma unroll
        for (int i = 0; i < 4; i++) {
            float4 v = *(const float4*)(qr + i * 4);
            QS(kq + i * 4 + 0, strow) = v.x; QS(kq + i * 4 + 1, strow) = v.y;
            QS(kq + i * 4 + 2, strow) = v.z; QS(kq + i * 4 + 3, strow) = v.w;
        }
        const float* kr = Kb + (size_t)strow * DMODEL + kq;
#pragma unroll
        for (int i = 0; i < 4; i++) {
            float4 v = *(const float4*)(kr + i * 4);
            KS(0, kq + i * 4 + 0, strow) = v.x; KS(0, kq + i * 4 + 1, strow) = v.y;
            KS(0, kq + i * 4 + 2, strow) = v.z; KS(0, kq + i * 4 + 3, strow) = v.w;
        }
        // mask chunk 0 via cp.async
        const int moff = stq * 16;   // ints
        const int* msrc = mask + ((size_t)b * SEQ + (m0 + strow)) * SEQ + moff;
        const unsigned mdst = sbase + (unsigned)(17408 + strow * 64 + moff) * 4u;
#pragma unroll
        for (int w = 0; w < 4; w++) CP_ASYNC16(mdst + w * 16u, msrc + w * 4);
        CP_COMMIT();
        CP_WAIT0();
    }
    __syncthreads();

    // per-warp row state: 8 rows, one sorted list entry per lane
    float lv[8]; int li[8];

#pragma unroll 1
    for (int c = 0; c < NCHUNK; c++) {
        const int cur = c & 1;
        const int nxt = cur ^ 1;

        // ---- prefetch K(c+1) into regs, mask(c+1) via cp.async ----
        float4 kp0, kp1, kp2, kp3;
        if (c + 1 < NCHUNK) {
            const int koff = stq << 4;
            const float* kr = Kb + (size_t)((c + 1) * CHUNK + strow) * DMODEL + koff;
            kp0 = *(const float4*)(kr);
            kp1 = *(const float4*)(kr + 4);
            kp2 = *(const float4*)(kr + 8);
            kp3 = *(const float4*)(kr + 12);
            const int moff = stq * 16;
            const int* msrc = mask + ((size_t)b * SEQ + (m0 + strow)) * SEQ
                              + (c + 1) * CHUNK + moff;
            const unsigned mdst = sbase + (unsigned)(17408 + nxt * 4096 + strow * 64 + moff) * 4u;
#pragma unroll
            for (int w = 0; w < 4; w++) CP_ASYNC16(mdst + w * 16u, msrc + w * 4);
            CP_COMMIT();
        }

        // ---- GEMM: 64x64 chunk, 4x4/thread, k ascending, init at k==0 (bitwise R6) ----
        float acc[4][4];
#pragma unroll 8
        for (int kk = 0; kk < 64; kk++) {
            float a[4], w[4];
            *(float4*)(a) = *(const float4*)&QS(kk, tr * 4);
            *(float4*)(w) = *(const float4*)&KS(cur, kk, tc * 4);
            if (kk == 0) {
#pragma unroll
                for (int i = 0; i < 4; i++)
#pragma unroll
                    for (int j = 0; j < 4; j++) acc[i][j] = a[i] * w[j];
            } else {
#pragma unroll
                for (int i = 0; i < 4; i++)
#pragma unroll
                    for (int j = 0; j < 4; j++) acc[i][j] += a[i] * w[j];
            }
        }
#pragma unroll
        for (int i = 0; i < 4; i++) {
            float4 o;
            o.x = acc[i][0] * 0.125f; o.y = acc[i][1] * 0.125f;
            o.z = acc[i][2] * 0.125f; o.w = acc[i][3] * 0.125f;
            *(float4*)&SB(tr * 4 + i, tc * 4) = o;
        }

        // ---- store prefetched K into Ks[nxt] ----
        if (c + 1 < NCHUNK) {
            const int kq = stq << 4;
            KS(nxt, kq + 0, strow) = kp0.x; KS(nxt, kq + 1, strow) = kp0.y;
            KS(nxt, kq + 2, strow) = kp0.z; KS(nxt, kq + 3, strow) = kp0.w;
            KS(nxt, kq + 4, strow) = kp1.x; KS(nxt, kq + 5, strow) = kp1.y;
            KS(nxt, kq + 6, strow) = kp1.z; KS(nxt, kq + 7, strow) = kp1.w;
            KS(nxt, kq + 8, strow) = kp2.x; KS(nxt, kq + 9, strow) = kp2.y;
            KS(nxt, kq + 10, strow) = kp2.z; KS(nxt, kq + 11, strow) = kp2.w;
            KS(nxt, kq + 12, strow) = kp3.x; KS(nxt, kq + 13, strow) = kp3.y;
            KS(nxt, kq + 14, strow) = kp3.z; KS(nxt, kq + 15, strow) = kp3.w;
        }
        __syncthreads();   // Sb + Ks[nxt] visible

        // ---- scan: each warp updates its 8 rows' sorted top-32 lists ----
#pragma unroll
        for (int i = 0; i < 8; i++) {
            const int r = warp * 8 + i;
            // pass 0: cols 0..31
            {
                float v = SB(r, lane);
                if (MS(cur, r, lane) == 0) v = -1e9f;
                const int idx = c * CHUNK + lane;
                if (c == 0) {
                    lv[i] = v; li[i] = idx;
                    // bitonic sort 32 desc under (v desc, idx asc)
#pragma unroll
                    for (int k = 2; k <= 32; k <<= 1) {
#pragma unroll
                        for (int j = k >> 1; j > 0; j >>= 1) {
                            float pv = __shfl_xor_sync(0xffffffffu, lv[i], j);
                            int   pi = __shfl_xor_sync(0xffffffffu, li[i], j);
                            const bool lower = ((lane & j) == 0);
                            const bool wantLargerLower = ((lane & k) == 0);
                            const bool iWin = (lv[i] > pv) || (lv[i] == pv && li[i] < pi);
                            if (iWin != (lower == wantLargerLower)) { lv[i] = pv; li[i] = pi; }
                        }
                    }
                } else {
                    topk_insert_pass(v, idx, lv[i], li[i], lane);
                }
            }
            // pass 1: cols 32..63
            {
                float v = SB(r, 32 + lane);
                if (MS(cur, r, 32 + lane) == 0) v = -1e9f;
                const int idx = c * CHUNK + 32 + lane;
                topk_insert_pass(v, idx, lv[i], li[i], lane);
            }
        }
        CP_WAIT0();        // mask(c+1) landed
        __syncthreads();   // Sb free for next chunk
    }

    // ---- epilogue: softmax + V gather per row (op order identical to R5/R7 gather) ----
    const float* vb = g_v + (size_t)b * SEQ * DMODEL + h * DHEAD;
#pragma unroll 1
    for (int i = 0; i < 8; i++) {
        const int q = m0 + warp * 8 + i;
        const float vmax = __shfl_sync(0xffffffffu, lv[i], 0);
        float e = expf(lv[i] - vmax);
        float ssum = e;
#pragma unroll
        for (int off = 16; off; off >>= 1) ssum += __shfl_xor_sync(0xffffffffu, ssum, off);
        const float p = e / ssum;

        float acc0 = 0.f, acc1 = 0.f;
#pragma unroll 4
        for (int j = 0; j < TOPK; j++) {
            float pj = __shfl_sync(0xffffffffu, p, j);
            int   ij = __shfl_sync(0xffffffffu, li[i], j);
            const float* vr = vb + (size_t)ij * DMODEL;
            acc0 += pj * vr[lane];
            acc1 += pj * vr[lane + 32];
        }
        float* crow = g_ctx + ((size_t)(b * SEQ + q)) * DMODEL + h * DHEAD;
        crow[lane]      = acc0;
        crow[lane + 32] = acc1;
    }
}

// =======================================================================================
// FAST fp32 NT GEMM (256 thr, 8x8 microtile) — output projection only (unchanged).
// =======================================================================================
__global__ __launch_bounds__(256, 2) void out_gemm_kernel(
    float* __restrict__ C, const float* __restrict__ W, const float* __restrict__ bias)
{
    __shared__ float As[16][132];
    __shared__ float Ws[16][132];
    const float* A = g_ctx;
    const int tid = threadIdx.x;
    const int m0 = blockIdx.y * 128;
    const int n0 = blockIdx.x * 128;
    const int tr = tid >> 4;
    const int tc = tid & 15;
    float acc[8][8];
#pragma unroll
    for (int i = 0; i < 8; i++)
#pragma unroll
        for (int j = 0; j < 8; j++) acc[i][j] = 0.f;

    const int r0 = tid >> 2;
    const int c0 = (tid & 3) << 2;

    for (int k0 = 0; k0 < 1024; k0 += 16) {
#pragma unroll
        for (int t = 0; t < 2; t++) {
            int r = r0 + t * 64;
            float4 av = *(const float4*)(A + (size_t)(m0 + r) * 1024 + k0 + c0);
            As[c0 + 0][r] = av.x; As[c0 + 1][r] = av.y;
            As[c0 + 2][r] = av.z; As[c0 + 3][r] = av.w;
            float4 wv = *(const float4*)(W + (size_t)(n0 + r) * 1024 + k0 + c0);
            Ws[c0 + 0][r] = wv.x; Ws[c0 + 1][r] = wv.y;
            Ws[c0 + 2][r] = wv.z; Ws[c0 + 3][r] = wv.w;
        }
        __syncthreads();
#pragma unroll
        for (int k = 0; k < 16; k++) {
            float a[8], w[8];
            *(float4*)(a)     = *(const float4*)&As[k][tr * 8];
            *(float4*)(a + 4) = *(const float4*)&As[k][tr * 8 + 4];
            *(float4*)(w)     = *(const float4*)&Ws[k][tc * 8];
            *(float4*)(w + 4) = *(const float4*)&Ws[k][tc * 8 + 4];
#pragma unroll
            for (int i = 0; i < 8; i++)
#pragma unroll
                for (int j = 0; j < 8; j++)
                    acc[i][j] += a[i] * w[j];
        }
        __syncthreads();
    }

    float bb[8];
#pragma unroll
    for (int j = 0; j < 8; j++) bb[j] = bias[n0 + tc * 8 + j];
#pragma unroll
    for (int i = 0; i < 8; i++) {
        float4 o0, o1;
        o0.x = acc[i][0] + bb[0]; o0.y = acc[i][1] + bb[1];
        o0.z = acc[i][2] + bb[2]; o0.w = acc[i][3] + bb[3];
        o1.x = acc[i][4] + bb[4]; o1.y = acc[i][5] + bb[5];
        o1.z = acc[i][6] + bb[6]; o1.w = acc[i][7] + bb[7];
        float* crow = C + (size_t)(m0 + tr * 8 + i) * 1024 + n0 + tc * 8;
        *(float4*)crow       = o0;
        *(float4*)(crow + 4) = o1;
    }
}

// ---------------- launch ----------------
extern "C" void kernel_launch(void* const* d_in, const int* in_sizes, int n_in,
                              void* d_out, int out_size)
{
    const float* query = (const float*)d_in[0];
    const float* key   = (const float*)d_in[1];
    const float* value = (const float*)d_in[2];
    const float* Wq    = (const float*)d_in[3];
    const float* bq    = (const float*)d_in[4];
    const float* Wk    = (const float*)d_in[5];
    const float* bk    = (const float*)d_in[6];
    const float* Wv    = (const float*)d_in[7];
    const float* bv    = (const float*)d_in[8];
    const float* Wo    = (const float*)d_in[9];
    const float* bo    = (const float*)d_in[10];
    const int*   mask  = (const int*)d_in[11];
    (void)in_sizes; (void)n_in; (void)out_size;

    cudaFuncSetAttribute(fused_attn_kernel,
                         cudaFuncAttributeMaxDynamicSharedMemorySize, FUSED_SMEM);

    dim3 gp(DMODEL / 64, (BATCH * SEQ) / 128, 3);          // (16, 32, 3)
    proj_kernel<<<gp, 256>>>(query, key, value, Wq, bq, Wk, bk, Wv, bv);

    dim3 gf(SEQ / BLK_M, BATCH * NHEAD);                   // (32, 32)
    fused_attn_kernel<<<gf, 256, FUSED_SMEM>>>(mask);

    dim3 go(DMODEL / 128, (BATCH * SEQ) / 128);            // (8, 32)
    out_gemm_kernel<<<go, 256>>>((float*)d_out, Wo, bo);
}

// round 9
// speedup vs baseline: 3.0295x; 1.5730x over previous
#include <cuda_runtime.h>
#include <math.h>
#include <float.h>

#define BATCH  2
#define SEQ    2048
#define DMODEL 1024
#define NHEAD  16
#define DHEAD  64
#define TOPK   32

// ---------------- device scratch ----------------
__device__ float g_q[(size_t)BATCH * SEQ * DMODEL];
__device__ float g_k[(size_t)BATCH * SEQ * DMODEL];
__device__ float g_v[(size_t)BATCH * SEQ * DMODEL];
__device__ float g_ctx[(size_t)BATCH * SEQ * DMODEL];
__device__ float g_s[(size_t)BATCH * NHEAD * SEQ * SEQ];  // 536 MB score scratch

// =======================================================================================
// Projection kernel v3 (Q, K, V via blockIdx.z). 128x128 tile, 256 thr, 8x8 microtile
// (1.0 B/FLOP smem traffic -> ~41 TF/s crossbar cap), double-buffered SMEM with
// register prefetch, ONE barrier per 16-k slab. 1 CTA/SM (~185 regs).
// Per-output FFMA sequence BITWISE IDENTICAL to R2/R4/R5:
//   p = partial over ascending 64-k chunk (init with product at chunk start, i.e.
//   slab s%4==0 at kk==0), acc += p at slab s%4==3; 16 folds; out = acc + bias.
// =======================================================================================
__global__ __launch_bounds__(256, 1) void proj_kernel(
    const float* __restrict__ query, const float* __restrict__ key,
    const float* __restrict__ value,
    const float* __restrict__ Wq, const float* __restrict__ bq,
    const float* __restrict__ Wk, const float* __restrict__ bk,
    const float* __restrict__ Wv, const float* __restrict__ bv)
{
    __shared__ float As[2][16][132];
    __shared__ float Ws[2][16][132];

    const int z = blockIdx.z;
    const float* A    = (z == 0) ? query : (z == 1) ? key : value;
    const float* W    = (z == 0) ? Wq    : (z == 1) ? Wk  : Wv;
    const float* bias = (z == 0) ? bq    : (z == 1) ? bk  : bv;
    float*       C    = (z == 0) ? g_q   : (z == 1) ? g_k : g_v;

    const int tid = threadIdx.x;          // 0..255
    const int m0 = blockIdx.y * 128;
    const int n0 = blockIdx.x * 128;
    const int tr = tid >> 4;              // 0..15 -> rows tr*8..+7
    const int tc = tid & 15;              // 0..15 -> cols tc*8..+7

    // loaders: 128 rows x 16 k per slab for A and W; 2 float4 each per thread
    const int r0 = tid >> 1;              // 0..127
    const int c0 = (tid & 1) << 3;        // 0 or 8

    const float* Arow = A + (size_t)(m0 + r0) * 1024 + c0;
    const float* Wrow = W + (size_t)(n0 + r0) * 1024 + c0;

    // prologue: slab 0 -> buffer 0
    {
        float4 a0 = *(const float4*)(Arow);
        float4 a1 = *(const float4*)(Arow + 4);
        As[0][c0 + 0][r0] = a0.x; As[0][c0 + 1][r0] = a0.y;
        As[0][c0 + 2][r0] = a0.z; As[0][c0 + 3][r0] = a0.w;
        As[0][c0 + 4][r0] = a1.x; As[0][c0 + 5][r0] = a1.y;
        As[0][c0 + 6][r0] = a1.z; As[0][c0 + 7][r0] = a1.w;
        float4 w0 = *(const float4*)(Wrow);
        float4 w1 = *(const float4*)(Wrow + 4);
        Ws[0][c0 + 0][r0] = w0.x; Ws[0][c0 + 1][r0] = w0.y;
        Ws[0][c0 + 2][r0] = w0.z; Ws[0][c0 + 3][r0] = w0.w;
        Ws[0][c0 + 4][r0] = w1.x; Ws[0][c0 + 5][r0] = w1.y;
        Ws[0][c0 + 6][r0] = w1.z; Ws[0][c0 + 7][r0] = w1.w;
    }
    __syncthreads();

    float acc[8][8], p[8][8];
#pragma unroll
    for (int i = 0; i < 8; i++)
#pragma unroll
        for (int j = 0; j < 8; j++) acc[i][j] = 0.f;

#pragma unroll 1
    for (int s = 0; s < 64; s++) {
        const int cur = s & 1;
        float4 na0, na1, nw0, nw1;
        if (s < 63) {                      // prefetch next slab into registers
            na0 = *(const float4*)(Arow + (size_t)(s + 1) * 16);
            na1 = *(const float4*)(Arow + (size_t)(s + 1) * 16 + 4);
            nw0 = *(const float4*)(Wrow + (size_t)(s + 1) * 16);
            nw1 = *(const float4*)(Wrow + (size_t)(s + 1) * 16 + 4);
        }
        const bool pinit = ((s & 3) == 0);
#pragma unroll
        for (int kk = 0; kk < 16; kk++) {
            float a[8], w[8];
            *(float4*)(a)     = *(const float4*)&As[cur][kk][tr * 8];
            *(float4*)(a + 4) = *(const float4*)&As[cur][kk][tr * 8 + 4];
            *(float4*)(w)     = *(const float4*)&Ws[cur][kk][tc * 8];
            *(float4*)(w + 4) = *(const float4*)&Ws[cur][kk][tc * 8 + 4];
            if (pinit && kk == 0) {
#pragma unroll
                for (int i = 0; i < 8; i++)
#pragma unroll
                    for (int j = 0; j < 8; j++) p[i][j] = a[i] * w[j];
            } else {
#pragma unroll
                for (int i = 0; i < 8; i++)
#pragma unroll
                    for (int j = 0; j < 8; j++) p[i][j] += a[i] * w[j];
            }
        }
        if ((s & 3) == 3) {
#pragma unroll
            for (int i = 0; i < 8; i++)
#pragma unroll
                for (int j = 0; j < 8; j++) acc[i][j] += p[i][j];
        }
        if (s < 63) {
            const int nxt = cur ^ 1;
            As[nxt][c0 + 0][r0] = na0.x; As[nxt][c0 + 1][r0] = na0.y;
            As[nxt][c0 + 2][r0] = na0.z; As[nxt][c0 + 3][r0] = na0.w;
            As[nxt][c0 + 4][r0] = na1.x; As[nxt][c0 + 5][r0] = na1.y;
            As[nxt][c0 + 6][r0] = na1.z; As[nxt][c0 + 7][r0] = na1.w;
            Ws[nxt][c0 + 0][r0] = nw0.x; Ws[nxt][c0 + 1][r0] = nw0.y;
            Ws[nxt][c0 + 2][r0] = nw0.z; Ws[nxt][c0 + 3][r0] = nw0.w;
            Ws[nxt][c0 + 4][r0] = nw1.x; Ws[nxt][c0 + 5][r0] = nw1.y;
            Ws[nxt][c0 + 6][r0] = nw1.z; Ws[nxt][c0 + 7][r0] = nw1.w;
        }
        __syncthreads();
    }

    float bb[8];
#pragma unroll
    for (int j = 0; j < 8; j++) bb[j] = bias[n0 + tc * 8 + j];
#pragma unroll
    for (int i = 0; i < 8; i++) {
        float4 o0, o1;
        o0.x = acc[i][0] + bb[0]; o0.y = acc[i][1] + bb[1];
        o0.z = acc[i][2] + bb[2]; o0.w = acc[i][3] + bb[3];
        o1.x = acc[i][4] + bb[4]; o1.y = acc[i][5] + bb[5];
        o1.z = acc[i][6] + bb[6]; o1.w = acc[i][7] + bb[7];
        float* crow = C + (size_t)(m0 + tr * 8 + i) * 1024 + n0 + tc * 8;
        *(float4*)crow       = o0;
        *(float4*)(crow + 4) = o1;
    }
}

// =======================================================================================
// Scores kernel (verbatim R5, proven): per (b,h), 128x128 tile of Q*K^T*0.125.
// 256 thr, 8x8 microtile, 2 CTAs/SM, K=64 staged once -> 1 barrier, straight FFMA loop.
// =======================================================================================
__global__ __launch_bounds__(256, 2) void scores_gemm_kernel()
{
    extern __shared__ float sm[];
    float (*Qs)[132] = (float(*)[132])sm;               // [64][132]
    float (*Ks)[132] = (float(*)[132])(sm + 64 * 132);  // [64][132]

    const int z = blockIdx.z;        // b*NHEAD + h
    const int b = z >> 4;
    const int h = z & 15;
    const int tid = threadIdx.x;     // 0..255
    const int m0 = blockIdx.y * 128;
    const int n0 = blockIdx.x * 128;
    const int tr = tid >> 4;
    const int tc = tid & 15;

    const int r    = tid >> 1;           // 0..127
    const int half = (tid & 1) << 5;     // 0 or 32
    const float* Qrow = g_q + (size_t)(b * SEQ + m0 + r) * DMODEL + h * DHEAD + half;
    const float* Krow = g_k + (size_t)(b * SEQ + n0 + r) * DMODEL + h * DHEAD + half;
#pragma unroll
    for (int i = 0; i < 8; i++) {
        float4 qv = *(const float4*)(Qrow + i * 4);
        const int kc = half + i * 4;
        Qs[kc + 0][r] = qv.x; Qs[kc + 1][r] = qv.y;
        Qs[kc + 2][r] = qv.z; Qs[kc + 3][r] = qv.w;
        float4 kv = *(const float4*)(Krow + i * 4);
        Ks[kc + 0][r] = kv.x; Ks[kc + 1][r] = kv.y;
        Ks[kc + 2][r] = kv.z; Ks[kc + 3][r] = kv.w;
    }
    __syncthreads();

    float acc[8][8];
#pragma unroll 4
    for (int kk = 0; kk < 64; kk++) {
        float a[8], w[8];
        *(float4*)(a)     = *(const float4*)&Qs[kk][tr * 8];
        *(float4*)(a + 4) = *(const float4*)&Qs[kk][tr * 8 + 4];
        *(float4*)(w)     = *(const float4*)&Ks[kk][tc * 8];
        *(float4*)(w + 4) = *(const float4*)&Ks[kk][tc * 8 + 4];
        if (kk == 0) {
#pragma unroll
            for (int i = 0; i < 8; i++)
#pragma unroll
                for (int j = 0; j < 8; j++) acc[i][j] = a[i] * w[j];
        } else {
#pragma unroll
            for (int i = 0; i < 8; i++)
#pragma unroll
                for (int j = 0; j < 8; j++) acc[i][j] += a[i] * w[j];
        }
    }

    float* Cz = g_s + (size_t)z * SEQ * SEQ;
#pragma unroll
    for (int i = 0; i < 8; i++) {
        float4 o0, o1;
        o0.x = acc[i][0] * 0.125f; o0.y = acc[i][1] * 0.125f;
        o0.z = acc[i][2] * 0.125f; o0.w = acc[i][3] * 0.125f;
        o1.x = acc[i][4] * 0.125f; o1.y = acc[i][5] * 0.125f;
        o1.z = acc[i][6] * 0.125f; o1.w = acc[i][7] * 0.125f;
        float* crow = Cz + (size_t)(m0 + tr * 8 + i) * SEQ + n0 + tc * 8;
        *(float4*)crow       = o0;
        *(float4*)(crow + 4) = o1;
    }
}

// =======================================================================================
// FAST fp32 NT GEMM (verbatim R5) — output projection only.
// =======================================================================================
__global__ __launch_bounds__(256, 2) void out_gemm_kernel(
    float* __restrict__ C, const float* __restrict__ W, const float* __restrict__ bias)
{
    __shared__ float As[16][132];
    __shared__ float Ws[16][132];
    const float* A = g_ctx;
    const int tid = threadIdx.x;
    const int m0 = blockIdx.y * 128;
    const int n0 = blockIdx.x * 128;
    const int tr = tid >> 4;
    const int tc = tid & 15;
    float acc[8][8];
#pragma unroll
    for (int i = 0; i < 8; i++)
#pragma unroll
        for (int j = 0; j < 8; j++) acc[i][j] = 0.f;

    const int r0 = tid >> 2;
    const int c0 = (tid & 3) << 2;

    for (int k0 = 0; k0 < 1024; k0 += 16) {
#pragma unroll
        for (int t = 0; t < 2; t++) {
            int r = r0 + t * 64;
            float4 av = *(const float4*)(A + (size_t)(m0 + r) * 1024 + k0 + c0);
            As[c0 + 0][r] = av.x; As[c0 + 1][r] = av.y;
            As[c0 + 2][r] = av.z; As[c0 + 3][r] = av.w;
            float4 wv = *(const float4*)(W + (size_t)(n0 + r) * 1024 + k0 + c0);
            Ws[c0 + 0][r] = wv.x; Ws[c0 + 1][r] = wv.y;
            Ws[c0 + 2][r] = wv.z; Ws[c0 + 3][r] = wv.w;
        }
        __syncthreads();
#pragma unroll
        for (int k = 0; k < 16; k++) {
            float a[8], w[8];
            *(float4*)(a)     = *(const float4*)&As[k][tr * 8];
            *(float4*)(a + 4) = *(const float4*)&As[k][tr * 8 + 4];
            *(float4*)(w)     = *(const float4*)&Ws[k][tc * 8];
            *(float4*)(w + 4) = *(const float4*)&Ws[k][tc * 8 + 4];
#pragma unroll
            for (int i = 0; i < 8; i++)
#pragma unroll
                for (int j = 0; j < 8; j++)
                    acc[i][j] += a[i] * w[j];
        }
        __syncthreads();
    }

    float bb[8];
#pragma unroll
    for (int j = 0; j < 8; j++) bb[j] = bias[n0 + tc * 8 + j];
#pragma unroll
    for (int i = 0; i < 8; i++) {
        float4 o0, o1;
        o0.x = acc[i][0] + bb[0]; o0.y = acc[i][1] + bb[1];
        o0.z = acc[i][2] + bb[2]; o0.w = acc[i][3] + bb[3];
        o1.x = acc[i][4] + bb[4]; o1.y = acc[i][5] + bb[5];
        o1.z = acc[i][6] + bb[6]; o1.w = acc[i][7] + bb[7];
        float* crow = C + (size_t)(m0 + tr * 8 + i) * 1024 + n0 + tc * 8;
        *(float4*)crow       = o0;
        *(float4*)(crow + 4) = o1;
    }
}

// ---------------- top-k(32) + softmax + V gather (verbatim R5) ----------------
__global__ __launch_bounds__(128) void topk_attn_kernel(const int* __restrict__ mask)
{
    __shared__ float sv[4][SEQ];
    __shared__ float selv[4][TOPK];
    __shared__ int   seli[4][TOPK];

    const int warp = threadIdx.x >> 5;
    const int lane = threadIdx.x & 31;
    const int rid = blockIdx.x * 4 + warp;     // (b*SEQ + q)*NHEAD + h
    const int h  = rid & 15;
    const int bq = rid >> 4;
    const int q  = bq & (SEQ - 1);
    const int b  = bq >> 11;

    const float* srow = g_s + ((size_t)(b * NHEAD + h) * SEQ + q) * SEQ;
    const int*   mrow = mask + ((size_t)b * SEQ + q) * SEQ;
    float* svw = sv[warp];

    for (int j = lane; j < SEQ; j += 32) {
        float v = srow[j];
        if (mrow[j] == 0) v = -1e9f;
        svw[j] = v;
    }
    __syncwarp();

    float mv = -INFINITY; int mi = 0x7fffffff;
    const int base = lane << 6;
#pragma unroll 8
    for (int j0 = 0; j0 < 64; j0++) {
        int j = base + ((j0 + lane) & 63);
        float v = svw[j];
        if (v > mv || (v == mv && j < mi)) { mv = v; mi = j; }
    }

    for (int it = 0; it < TOPK; it++) {
        float bv = mv; int bi = mi;
#pragma unroll
        for (int off = 16; off; off >>= 1) {
            float ov = __shfl_xor_sync(0xffffffffu, bv, off);
            int   oi = __shfl_xor_sync(0xffffffffu, bi, off);
            if (ov > bv || (ov == bv && oi < bi)) { bv = ov; bi = oi; }
        }
        if (lane == 0) {
            selv[warp][it] = bv;
            seli[warp][it] = bi;
            svw[bi] = -INFINITY;
        }
        const int owner = bi >> 6;
        __syncwarp();
        const int i0 = (owner << 6) + (lane << 1);
        float2 c = *(const float2*)&svw[i0];
        float nv; int ni;
        if (c.x >= c.y) { nv = c.x; ni = i0; } else { nv = c.y; ni = i0 + 1; }
#pragma unroll
        for (int off = 16; off; off >>= 1) {
            float ov = __shfl_xor_sync(0xffffffffu, nv, off);
            int   oi = __shfl_xor_sync(0xffffffffu, ni, off);
            if (ov > nv || (ov == nv && oi < ni)) { nv = ov; ni = oi; }
        }
        if (lane == owner) { mv = nv; mi = ni; }
    }
    __syncwarp();

    const float vsel = selv[warp][lane];
    const float vmax = selv[warp][0];
    float e = expf(vsel - vmax);
    float ssum = e;
#pragma unroll
    for (int off = 16; off; off >>= 1) ssum += __shfl_xor_sync(0xffffffffu, ssum, off);
    const float p = e / ssum;

    const float* vb = g_v + (size_t)b * SEQ * DMODEL + h * DHEAD;
    float acc0 = 0.f, acc1 = 0.f;
#pragma unroll 4
    for (int j = 0; j < TOPK; j++) {
        float pj = __shfl_sync(0xffffffffu, p, j);
        int idx = seli[warp][j];
        const float* vr = vb + (size_t)idx * DMODEL;
        acc0 += pj * vr[lane];
        acc1 += pj * vr[lane + 32];
    }
    float* crow = g_ctx + ((size_t)(b * SEQ + q)) * DMODEL + h * DHEAD;
    crow[lane]      = acc0;
    crow[lane + 32] = acc1;
}

// ---------------- launch ----------------
extern "C" void kernel_launch(void* const* d_in, const int* in_sizes, int n_in,
                              void* d_out, int out_size)
{
    const float* query = (const float*)d_in[0];
    const float* key   = (const float*)d_in[1];
    const float* value = (const float*)d_in[2];
    const float* Wq    = (const float*)d_in[3];
    const float* bq    = (const float*)d_in[4];
    const float* Wk    = (const float*)d_in[5];
    const float* bk    = (const float*)d_in[6];
    const float* Wv    = (const float*)d_in[7];
    const float* bv    = (const float*)d_in[8];
    const float* Wo    = (const float*)d_in[9];
    const float* bo    = (const float*)d_in[10];
    const int*   mask  = (const int*)d_in[11];
    (void)in_sizes; (void)n_in; (void)out_size;

    const int smem_scores = 2 * 64 * 132 * sizeof(float);  // 67584 B
    cudaFuncSetAttribute(scores_gemm_kernel,
                         cudaFuncAttributeMaxDynamicSharedMemorySize, smem_scores);

    dim3 gp(DMODEL / 128, (BATCH * SEQ) / 128, 3);         // (8, 32, 3)
    proj_kernel<<<gp, 256>>>(query, key, value, Wq, bq, Wk, bk, Wv, bv);

    dim3 gs(SEQ / 128, SEQ / 128, BATCH * NHEAD);          // (16, 16, 32)
    scores_gemm_kernel<<<gs, 256, smem_scores>>>();

    topk_attn_kernel<<<(BATCH * SEQ * NHEAD) / 4, 128>>>(mask);

    dim3 go(DMODEL / 128, (BATCH * SEQ) / 128);            // (8, 32)
    out_gemm_kernel<<<go, 256>>>((float*)d_out, Wo, bo);
}